// round 1
// baseline (speedup 1.0000x reference)
#include <cuda_runtime.h>
#include <cstdint>

// Fixed problem shape (from reference): N=320000, C=64, B=4, NY=496, NX=432, NZ=1
#define NY_   496
#define NX_   432
#define C_    64
#define B_    4
#define NCELL (B_ * NY_ * NX_)        // 857,088 cells
// out_size = B*C*NY*NX = 54,853,632 floats

// Scratch: winner point-index per output cell (-1 = empty).
// Static __device__ array (allocation-free per harness rules). 3.4 MB.
__device__ int g_winner[NCELL];

// ---------------------------------------------------------------------------
// Kernel 1: init winner to -1 (vectorized int4). NCELL % 4 == 0.
// ---------------------------------------------------------------------------
__global__ void init_winner_kernel() {
    int tid = blockIdx.x * blockDim.x + threadIdx.x;
    if (tid < NCELL / 4) {
        reinterpret_cast<int4*>(g_winner)[tid] = make_int4(-1, -1, -1, -1);
    }
}

// ---------------------------------------------------------------------------
// Kernel 2: atomicMax scatter of point indices. Last-write-wins semantics of
// sequential jnp .at[].set == highest point index wins per cell.
// coors layout: [N,4] int32 rows (b, z, y, x); NZ=1 so z==0 always.
// ---------------------------------------------------------------------------
__global__ void scatter_winner_kernel(const int* __restrict__ coors, int n) {
    int i = blockIdx.x * blockDim.x + threadIdx.x;
    if (i < n) {
        int4 cz = *reinterpret_cast<const int4*>(coors + 4 * i);  // (b, z, y, x)
        int cell = (cz.x * NY_ + cz.z) * NX_ + cz.w;
        atomicMax(&g_winner[cell], i);
    }
}

// ---------------------------------------------------------------------------
// Kernel 3: fused zero + gather. One float4 (4 consecutive x) per thread.
// Output layout: out[((b*C + c)*NY + y)*NX + x].
// winner layout: winner[(b*NY + y)*NX + x]  -> same x-run, reused across 64 c.
// Winner array (3.4 MB) and features (82 MB) are L2-resident on B200 (126 MB).
// ---------------------------------------------------------------------------
__global__ void gather_kernel(const float* __restrict__ feat,
                              float* __restrict__ out) {
    // total threads = out_size/4 = 13,713,408
    int tid = blockIdx.x * blockDim.x + threadIdx.x;
    const int NQ = (B_ * C_ * NY_ * NX_) / 4;
    if (tid >= NQ) return;

    int idx = tid * 4;                       // element index, x-aligned to 4
    int x   = idx % NX_;
    int r1  = idx / NX_;
    int y   = r1 % NY_;
    int r2  = r1 / NY_;
    int c   = r2 % C_;
    int b   = r2 / C_;

    int cell = (b * NY_ + y) * NX_ + x;      // multiple of 4 -> int4 aligned
    int4 w = *reinterpret_cast<const int4*>(g_winner + cell);

    float4 v;
    v.x = (w.x < 0) ? 0.0f : __ldg(feat + (size_t)w.x * C_ + c);
    v.y = (w.y < 0) ? 0.0f : __ldg(feat + (size_t)w.y * C_ + c);
    v.z = (w.z < 0) ? 0.0f : __ldg(feat + (size_t)w.z * C_ + c);
    v.w = (w.w < 0) ? 0.0f : __ldg(feat + (size_t)w.w * C_ + c);

    *reinterpret_cast<float4*>(out + idx) = v;
}

// ---------------------------------------------------------------------------
extern "C" void kernel_launch(void* const* d_in, const int* in_sizes, int n_in,
                              void* d_out, int out_size) {
    const float* feat  = (const float*)d_in[0];   // [N, 64] float32
    const int*   coors = (const int*)d_in[1];     // [N, 4] int32
    (void)n_in;

    int n = in_sizes[1] / 4;                      // number of points

    // 1) winner = -1
    {
        int threads = 256;
        int blocks  = (NCELL / 4 + threads - 1) / threads;
        init_winner_kernel<<<blocks, threads>>>();
    }
    // 2) atomicMax point index per cell
    {
        int threads = 256;
        int blocks  = (n + threads - 1) / threads;
        scatter_winner_kernel<<<blocks, threads>>>(coors, n);
    }
    // 3) fused zero + gather into output
    {
        int threads = 256;
        int nq = out_size / 4;
        int blocks = (nq + threads - 1) / threads;
        gather_kernel<<<blocks, threads>>>(feat, (float*)d_out);
    }
}

// round 5
// speedup vs baseline: 1.5263x; 1.5263x over previous
#include <cuda_runtime.h>
#include <cstdint>

// Fixed problem shape: N=320000, C=64, B=4, NY=496, NX=432, NZ=1
#define NY_   496
#define NX_   432
#define C_    64
#define B_    4
#define NCELL (B_ * NY_ * NX_)        // 857,088 cells

#define TX    48                      // cells per tile (432 = 9 * 48)
#define NTX   (NX_ / TX)              // 9 tiles per row
#define PAD   49                      // SMEM row pitch (48+1, avoids conflicts)

// Scratch: winner point-index per output cell (-1 = empty). 3.4 MB.
// Stored as int4 to guarantee 16 B alignment for vectorized access.
__device__ int4 g_winner4[NCELL / 4];

// ---------------------------------------------------------------------------
// Kernel 1: init winner to -1 (int4 vectorized). NCELL % 4 == 0.
// ---------------------------------------------------------------------------
__global__ void init_winner_kernel() {
    int tid = blockIdx.x * blockDim.x + threadIdx.x;
    if (tid < NCELL / 4) {
        g_winner4[tid] = make_int4(-1, -1, -1, -1);
    }
}

// ---------------------------------------------------------------------------
// Kernel 2: atomicMax scatter of point indices (last-write-wins == max index).
// coors rows: (b, z, y, x), z == 0 always (NZ=1).
// ---------------------------------------------------------------------------
__global__ void scatter_winner_kernel(const int* __restrict__ coors, int n) {
    int i = blockIdx.x * blockDim.x + threadIdx.x;
    if (i < n) {
        int4 cz = *reinterpret_cast<const int4*>(coors + 4 * i);
        int cell = (cz.x * NY_ + cz.z) * NX_ + cz.w;
        atomicMax(reinterpret_cast<int*>(g_winner4) + cell, i);
    }
}

// ---------------------------------------------------------------------------
// Kernel 3: tiled gather + transpose.
// One block = 48 cells along x (fixed b, y) x all 64 channels.
//   Phase 1: winners -> SMEM (12 int4).
//   Phase 2: per winning cell, read the full 256 B feature row coalesced
//            (16 lanes x float4 per cell), scatter into transposed SMEM tile.
//   Phase 3: write output as float4 along x, per channel (coalesced STG.128).
// ---------------------------------------------------------------------------
__global__ __launch_bounds__(256) void gather_tile_kernel(
    const float* __restrict__ feat, float* __restrict__ out) {

    __shared__ float tile[C_ * PAD];   // tile[c*PAD + j], 12.25 KB
    __shared__ int   sw[TX];

    int t    = threadIdx.x;
    int bid  = blockIdx.x;                 // 0 .. B*NY*NTX-1
    int tx   = bid % NTX;
    int y    = (bid / NTX) % NY_;
    int b    = bid / (NTX * NY_);
    int x0   = tx * TX;
    int cell0 = (b * NY_ + y) * NX_ + x0;  // multiple of 16

    // Phase 1: load 48 winners (12 int4); cell0/4 is the int4 index.
    if (t < TX / 4) {
        int4 w4 = g_winner4[cell0 / 4 + t];
        *reinterpret_cast<int4*>(sw + 4 * t) = w4;
    }
    __syncthreads();

    // Phase 2: 48 cells * 16 float4 = 768 loads, 3 per thread.
    // q -> (cell j = q/16, f4 = q%16). Lanes 0..15 share a cell => the 256 B
    // feature row is read in one fully-coalesced sweep, each row exactly once.
    #pragma unroll
    for (int k = 0; k < 3; k++) {
        int q  = k * 256 + t;
        int j  = q >> 4;
        int f4 = q & 15;
        int w  = sw[j];
        float4 v = make_float4(0.f, 0.f, 0.f, 0.f);
        if (w >= 0) {
            v = *reinterpret_cast<const float4*>(feat + (size_t)w * C_ + f4 * 4);
        }
        int c0 = f4 * 4;
        tile[(c0 + 0) * PAD + j] = v.x;
        tile[(c0 + 1) * PAD + j] = v.y;
        tile[(c0 + 2) * PAD + j] = v.z;
        tile[(c0 + 3) * PAD + j] = v.w;
    }
    __syncthreads();

    // Phase 3: 64 channels * 12 float4-groups = 768 vector stores, 3/thread.
    // Consecutive threads -> consecutive x-groups => coalesced STG.128.
    size_t obase = ((size_t)(b * C_) * NY_ + y) * NX_ + x0;   // 16B aligned
    #pragma unroll
    for (int k = 0; k < 3; k++) {
        int idx = k * 256 + t;          // 0..767
        int c   = idx / (TX / 4);       // channel
        int g   = idx - c * (TX / 4);   // float4 group within the 48-run
        int j   = g * 4;
        const float* src = &tile[c * PAD + j];
        float4 v = make_float4(src[0], src[1], src[2], src[3]);
        *reinterpret_cast<float4*>(out + obase + (size_t)c * (NY_ * NX_) + j) = v;
    }
}

// ---------------------------------------------------------------------------
extern "C" void kernel_launch(void* const* d_in, const int* in_sizes, int n_in,
                              void* d_out, int out_size) {
    const float* feat  = (const float*)d_in[0];   // [N, 64] float32
    const int*   coors = (const int*)d_in[1];     // [N, 4] int32
    (void)n_in; (void)out_size;

    int n = in_sizes[1] / 4;

    {   // 1) winner = -1
        int threads = 256;
        int blocks  = (NCELL / 4 + threads - 1) / threads;
        init_winner_kernel<<<blocks, threads>>>();
    }
    {   // 2) atomicMax point index per cell
        int threads = 256;
        int blocks  = (n + threads - 1) / threads;
        scatter_winner_kernel<<<blocks, threads>>>(coors, n);
    }
    {   // 3) tiled gather + transpose
        int blocks = B_ * NY_ * NTX;   // 17,856
        gather_tile_kernel<<<blocks, 256>>>(feat, (float*)d_out);
    }
}

// round 6
// speedup vs baseline: 1.8037x; 1.1817x over previous
#include <cuda_runtime.h>
#include <cstdint>

// Fixed problem shape: N=320000, C=64, B=4, NY=496, NX=432, NZ=1
#define NY_   496
#define NX_   432
#define C_    64
#define B_    4
#define NCELL (B_ * NY_ * NX_)        // 857,088 cells

#define CCH    16                     // channels per chunk
#define NCHUNK (C_ / CCH)             // 4 chunks
#define PITCH  436                    // SMEM pitch (432+4, multiple of 4 for LDS.128)
#define THREADS_G 512

// Scratch: winner point-index per output cell (-1 = empty). 3.4 MB.
// int4-typed for guaranteed 16 B alignment.
__device__ int4 g_winner4[NCELL / 4];

// ---------------------------------------------------------------------------
// Kernel 1: init winner to -1. 4 int4 (64 B) per thread.
// ---------------------------------------------------------------------------
__global__ void init_winner_kernel() {
    int tid = blockIdx.x * blockDim.x + threadIdx.x;
    const int NQ = NCELL / 4;           // 214,272 int4s
    int4 m1 = make_int4(-1, -1, -1, -1);
    #pragma unroll
    for (int k = 0; k < 4; k++) {
        int i = tid * 4 + k;
        if (i < NQ) g_winner4[i] = m1;
    }
}

// ---------------------------------------------------------------------------
// Kernel 2: atomicMax scatter of point indices (last-write-wins == max index).
// coors rows: (b, z, y, x), z == 0 always (NZ=1).
// ---------------------------------------------------------------------------
__global__ void scatter_winner_kernel(const int* __restrict__ coors, int n) {
    int i = blockIdx.x * blockDim.x + threadIdx.x;
    if (i < n) {
        int4 cz = *reinterpret_cast<const int4*>(coors + 4 * i);
        int cell = (cz.x * NY_ + cz.z) * NX_ + cz.w;
        atomicMax(reinterpret_cast<int*>(g_winner4) + cell, i);
    }
}

// ---------------------------------------------------------------------------
// Kernel 3: one block per (b, y) row — 432 cells x 64 channels, processed in
// 4 chunks of 16 channels through a transposed SMEM tile.
//   Phase 1 (once): 432 winners -> SMEM.
//   Phase 2 (per chunk): thread = cell; read 64 B feature slice (4x LDG.128,
//       fully coalesced within the row), transpose-store 16 scalars (stride-1,
//       conflict-free STS).
//   Phase 3 (per chunk): write 16 channels x 1728 B contiguous per channel,
//       LDS.128 + STG.128 fully coalesced.
// ---------------------------------------------------------------------------
__global__ __launch_bounds__(THREADS_G) void gather_row_kernel(
    const float* __restrict__ feat, float* __restrict__ out) {

    __shared__ int   sw[NX_];              // 432 winners
    __shared__ float tile[CCH * PITCH];    // 27.25 KB

    int t = threadIdx.x;
    int y = blockIdx.x % NY_;
    int b = blockIdx.x / NY_;
    int cell0 = (b * NY_ + y) * NX_;       // multiple of 4

    // Phase 1: 108 int4 loads of winners
    if (t < NX_ / 4) {
        *reinterpret_cast<int4*>(sw + 4 * t) = g_winner4[cell0 / 4 + t];
    }
    __syncthreads();

    size_t rowbase = ((size_t)(b * C_) * NY_ + y) * NX_;

    #pragma unroll
    for (int cc = 0; cc < C_; cc += CCH) {
        // Phase 2: gather + transpose 16-channel slice
        if (t < NX_) {
            int w = sw[t];
            float4 v0 = make_float4(0.f, 0.f, 0.f, 0.f);
            float4 v1 = v0, v2 = v0, v3 = v0;
            if (w >= 0) {
                const float4* src =
                    reinterpret_cast<const float4*>(feat + (size_t)w * C_ + cc);
                v0 = src[0]; v1 = src[1]; v2 = src[2]; v3 = src[3];
            }
            tile[ 0 * PITCH + t] = v0.x;  tile[ 1 * PITCH + t] = v0.y;
            tile[ 2 * PITCH + t] = v0.z;  tile[ 3 * PITCH + t] = v0.w;
            tile[ 4 * PITCH + t] = v1.x;  tile[ 5 * PITCH + t] = v1.y;
            tile[ 6 * PITCH + t] = v1.z;  tile[ 7 * PITCH + t] = v1.w;
            tile[ 8 * PITCH + t] = v2.x;  tile[ 9 * PITCH + t] = v2.y;
            tile[10 * PITCH + t] = v2.z;  tile[11 * PITCH + t] = v2.w;
            tile[12 * PITCH + t] = v3.x;  tile[13 * PITCH + t] = v3.y;
            tile[14 * PITCH + t] = v3.z;  tile[15 * PITCH + t] = v3.w;
        }
        __syncthreads();

        // Phase 3: 16 channels * 108 float4 = 1728 vector stores
        for (int q = t; q < CCH * (NX_ / 4); q += THREADS_G) {
            int k = q / (NX_ / 4);
            int g = q - k * (NX_ / 4);
            float4 v = *reinterpret_cast<const float4*>(&tile[k * PITCH + g * 4]);
            *reinterpret_cast<float4*>(
                out + rowbase + (size_t)(cc + k) * (NY_ * NX_) + g * 4) = v;
        }
        __syncthreads();
    }
}

// ---------------------------------------------------------------------------
extern "C" void kernel_launch(void* const* d_in, const int* in_sizes, int n_in,
                              void* d_out, int out_size) {
    const float* feat  = (const float*)d_in[0];   // [N, 64] float32
    const int*   coors = (const int*)d_in[1];     // [N, 4] int32
    (void)n_in; (void)out_size;

    int n = in_sizes[1] / 4;

    {   // 1) winner = -1 (64 B per thread)
        int threads = 256;
        int per_blk = threads * 4;
        int blocks  = (NCELL / 4 + per_blk - 1) / per_blk;   // 210
        init_winner_kernel<<<blocks, threads>>>();
    }
    {   // 2) atomicMax point index per cell
        int threads = 256;
        int blocks  = (n + threads - 1) / threads;
        scatter_winner_kernel<<<blocks, threads>>>(coors, n);
    }
    {   // 3) row gather + transpose
        int blocks = B_ * NY_;   // 1984
        gather_row_kernel<<<blocks, THREADS_G>>>(feat, (float*)d_out);
    }
}